// round 15
// baseline (speedup 1.0000x reference)
#include <cuda_runtime.h>
#include <cuda_bf16.h>
#include <cuda_fp16.h>

#define BB 64
#define TT 512
#define DD 512
#define HH 512
#define G3 1536

#define MTOT (BB * TT)
#define KW   (DD / 2)
#define XWRD (MTOT * KW)
#define WWRD (G3 * KW)

// ---------------- device scratch (no allocations allowed) ----------------
__device__ float    g_zi[2][TT][BB][G3];
__device__ unsigned g_xhi[XWRD];              // x fp16x2 hi
__device__ unsigned g_xlo[XWRD];              // x fp16x2 lo
__device__ unsigned g_whi[2][WWRD];           // W_ih fp16x2
__device__ unsigned g_h[2][2][BB * 256];      // h fp16x2 (single precision)
__device__ unsigned g_cnt[2][512];

// =================================================================
// helpers
// =================================================================
__device__ __forceinline__ unsigned pack2h(float a, float b) {
    __half2 t = __floats2half2_rn(a, b);
    return reinterpret_cast<unsigned&>(t);
}
__device__ __forceinline__ void split2h(float a, float b, unsigned& hi, unsigned& lo) {
    __half ha = __float2half_rn(a), hb = __float2half_rn(b);
    __half2 th = __halves2half2(ha, hb);
    hi = reinterpret_cast<unsigned&>(th);
    lo = pack2h(a - __half2float(ha), b - __half2float(hb));
}
__device__ __forceinline__ float lo16h(unsigned u) {
    __half2 t = reinterpret_cast<__half2&>(u);
    return __half2float(t.x);
}
__device__ __forceinline__ float hi16h(unsigned u) {
    __half2 t = reinterpret_cast<__half2&>(u);
    return __half2float(t.y);
}
__device__ __forceinline__ void mma16816h(float* c, const unsigned* a, const unsigned* b) {
    asm volatile(
        "mma.sync.aligned.m16n8k16.row.col.f32.f16.f16.f32 "
        "{%0,%1,%2,%3}, {%4,%5,%6,%7}, {%8,%9}, {%0,%1,%2,%3};"
        : "+f"(c[0]), "+f"(c[1]), "+f"(c[2]), "+f"(c[3])
        : "r"(a[0]), "r"(a[1]), "r"(a[2]), "r"(a[3]), "r"(b[0]), "r"(b[1]));
}
__device__ __forceinline__ void cp_async16(unsigned smem_addr, const void* gptr) {
    asm volatile("cp.async.cg.shared.global [%0], [%1], 16;\n"
                 :: "r"(smem_addr), "l"(gptr));
}
__device__ __forceinline__ void ldsm4(unsigned addr, unsigned* r) {
    asm volatile("ldmatrix.sync.aligned.m8n8.x4.shared.b16 {%0,%1,%2,%3}, [%4];"
        : "=r"(r[0]), "=r"(r[1]), "=r"(r[2]), "=r"(r[3]) : "r"(addr));
}
__device__ __forceinline__ void ldsm2(unsigned addr, unsigned* r) {
    asm volatile("ldmatrix.sync.aligned.m8n8.x2.shared.b16 {%0,%1}, [%2];"
        : "=r"(r[0]), "=r"(r[1]) : "r"(addr));
}

// =================================================================
// Kernel 0: split x into fp16 hi/lo; W_ih into fp16
// =================================================================
__global__ void convert_kernel(const float* __restrict__ x,
                               const float* __restrict__ w_fw,
                               const float* __restrict__ w_bw)
{
    const unsigned idx = blockIdx.x * 256 + threadIdx.x;
    if (idx < XWRD) {
        float2 v = reinterpret_cast<const float2*>(x)[idx];
        split2h(v.x, v.y, g_xhi[idx], g_xlo[idx]);
    } else {
        unsigned w = idx - XWRD;
        if (w < 2u * WWRD) {
            int d = w >= WWRD;
            unsigned o = d ? w - WWRD : w;
            const float* src = d ? w_bw : w_fw;
            float2 v = reinterpret_cast<const float2*>(src)[o];
            g_whi[d][o] = pack2h(v.x, v.y);
        }
    }
}

// =================================================================
// Kernel 1: zi = x @ W_ih^T + b_ih  (unchanged from R13/R14)
// =================================================================
#define GS_ROWW 20
#define A_MAT (128 * GS_ROWW)
#define B_MAT (64 * GS_ROWW)
#define GEMM_SMEM_WORDS (6 * A_MAT + 3 * B_MAT)
#define GEMM_SMEM_BYTES (GEMM_SMEM_WORDS * 4)

__global__ void __launch_bounds__(256, 2) gemm_zi_kernel(
    const float* __restrict__ b_fw, const float* __restrict__ b_bw)
{
    extern __shared__ unsigned gsm[];
    const int d = blockIdx.z;
    const float* __restrict__ Bi = d ? b_bw : b_fw;
    const unsigned* __restrict__ wh = g_whi[d];
    float* __restrict__ zi = &g_zi[d][0][0][0];

    const int m0 = blockIdx.y * 128;
    const int n0 = blockIdx.x * 64;
    const int tid  = threadIdx.x;
    const int warp = tid >> 5;
    const int lane = tid & 31;
    const int g    = lane >> 2;
    const int tg   = lane & 3;
    const int wm   = warp >> 2;
    const int wn   = warp & 3;

    const unsigned smem_base = (unsigned)__cvta_generic_to_shared(gsm);

    auto load_stage = [&](int kt, int s) {
#pragma unroll
        for (int i = 0; i < 5; i++) {
            int id = i * 256 + tid;
            const unsigned* src;
            unsigned dstw;
            if (id < 512) {
                int r = id >> 2, c = id & 3;
                src = g_xhi + (size_t)(m0 + r) * KW + kt * 16 + c * 4;
                dstw = s * A_MAT + r * GS_ROWW + c * 4;
            } else if (id < 1024) {
                int rem = id - 512;
                int r = rem >> 2, c = rem & 3;
                src = g_xlo + (size_t)(m0 + r) * KW + kt * 16 + c * 4;
                dstw = (3 + s) * A_MAT + r * GS_ROWW + c * 4;
            } else {
                int rem = id - 1024;
                int r = rem >> 2, c = rem & 3;
                src = wh + (size_t)(n0 + r) * KW + kt * 16 + c * 4;
                dstw = 6 * A_MAT + s * B_MAT + r * GS_ROWW + c * 4;
            }
            cp_async16(smem_base + dstw * 4, src);
        }
        asm volatile("cp.async.commit_group;\n");
    };

    float acc[4][2][4];
#pragma unroll
    for (int mi = 0; mi < 4; mi++)
#pragma unroll
        for (int ni = 0; ni < 2; ni++)
#pragma unroll
            for (int i = 0; i < 4; i++) acc[mi][ni][i] = 0.f;

    load_stage(0, 0);
    load_stage(1, 1);

    const int lr = lane & 15;
    const int lh = (lane >> 4) * 4;

    for (int kt = 0; kt < 16; ++kt) {
        if (kt < 15) asm volatile("cp.async.wait_group 1;\n");
        else         asm volatile("cp.async.wait_group 0;\n");
        __syncthreads();

        if (kt + 2 < 16) load_stage(kt + 2, (kt + 2) % 3);

        const int st = kt % 3;
        const unsigned baseXH = smem_base + (st * A_MAT) * 4;
        const unsigned baseXL = smem_base + ((3 + st) * A_MAT) * 4;
        const unsigned baseWH = smem_base + (6 * A_MAT + st * B_MAT) * 4;

#pragma unroll
        for (int kk = 0; kk < 2; ++kk) {
            const int kw = kk * 8 + lh;
            unsigned bhi[4];
            {
                unsigned off = ((wn * 16 + lr) * GS_ROWW + kw) * 4;
                ldsm4(baseWH + off, bhi);
            }
            unsigned be[2] = {bhi[0], bhi[2]};
            unsigned bo[2] = {bhi[1], bhi[3]};
#pragma unroll
            for (int mi = 0; mi < 4; mi++) {
                unsigned ahi[4], alo[4];
                unsigned off = ((wm * 64 + mi * 16 + lr) * GS_ROWW + kw) * 4;
                ldsm4(baseXH + off, ahi);
                ldsm4(baseXL + off, alo);
                mma16816h(acc[mi][0], ahi, be);
                mma16816h(acc[mi][0], alo, be);
                mma16816h(acc[mi][1], ahi, bo);
                mma16816h(acc[mi][1], alo, bo);
            }
        }
    }

    float bias[2][2];
#pragma unroll
    for (int ni = 0; ni < 2; ni++) {
        const int n = n0 + wn * 16 + ni * 8 + tg * 2;
        bias[ni][0] = Bi[n]; bias[ni][1] = Bi[n + 1];
    }
#pragma unroll
    for (int mi = 0; mi < 4; mi++) {
        const int row0 = m0 + wm * 64 + mi * 16 + g;
        const int row1 = row0 + 8;
        const int t0 = row0 & (TT - 1), b0r = row0 >> 9;
        const int t1 = row1 & (TT - 1), b1r = row1 >> 9;
        float* d0 = zi + (size_t)(t0 * BB + b0r) * G3;
        float* d1 = zi + (size_t)(t1 * BB + b1r) * G3;
#pragma unroll
        for (int ni = 0; ni < 2; ni++) {
            const int n = n0 + wn * 16 + ni * 8 + tg * 2;
            float2 v0, v1;
            v0.x = acc[mi][ni][0] + bias[ni][0];
            v0.y = acc[mi][ni][1] + bias[ni][1];
            v1.x = acc[mi][ni][2] + bias[ni][0];
            v1.y = acc[mi][ni][3] + bias[ni][1];
            *(float2*)(d0 + n) = v0;
            *(float2*)(d1 + n) = v1;
        }
    }
}

// =================================================================
// Kernel 2: persistent recurrence, SINGLE fp16 h carry:
// 3 MMAs + 3 LDSM per k16; staging halved (64 KB/block/step).
// =================================================================
#define WS_STRIDE 260
#define SM_W (24 * WS_STRIDE)
#define SM_H (64 * WS_STRIDE)
#define X_STRIDE 13
#define SM_X (4 * 32 * X_STRIDE)
#define RNN_SMEM_BYTES ((SM_W + SM_H + SM_X) * 4)

__global__ void __launch_bounds__(256, 1) rnn_kernel(
    const float* __restrict__ whh_fw, const float* __restrict__ whh_bw,
    const float* __restrict__ bhh_fw, const float* __restrict__ bhh_bw,
    float* __restrict__ out)
{
    extern __shared__ unsigned su[];
    unsigned* WHi = su;                          // [24][260] fp16x2
    unsigned* Hs  = su + SM_W;                   // [64][260] fp16x2
    float*    X   = (float*)(su + SM_W + SM_H);

    const int bid = blockIdx.x;
    const int d   = bid >> 6;
    const int sub = bid & 63;
    const int j0  = sub * 8;
    const float* __restrict__ W  = d ? whh_bw : whh_fw;
    const float* __restrict__ Bh = d ? bhh_bw : bhh_fw;

    const int tid  = threadIdx.x;
    const int warp = tid >> 5;
    const int lane = tid & 31;
    const int mt   = warp & 3;
    const int kh   = warp >> 2;
    const int g    = lane >> 2;
    const int tg   = lane & 3;

    auto bar = [&](int idx) {
        __syncthreads();
        if (tid == 0) {
            __threadfence();
            atomicAdd(&g_cnt[d][idx], 1u);
            unsigned v;
            do {
                v = *((volatile unsigned*)&g_cnt[d][idx]);
            } while (v != 0u && v < 64u);
            __threadfence();
        }
        __syncthreads();
    };

    // --- load W_hh slice as fp16 into SMEM (once) ---
    for (int idx = tid; idx < 24 * 256; idx += 256) {
        int r = idx >> 8, kw = idx & 255;
        int grow = ((r >> 3) << 9) + j0 + (r & 7);
        const float* wr = W + (size_t)grow * HH + kw * 2;
        WHi[r * WS_STRIDE + kw] = pack2h(wr[0], wr[1]);
    }

    const int b0i = mt * 16 + g;
    const int b1i = b0i + 8;
    const int jA  = j0 + tg * 2;
    const float2 bh_r = *(const float2*)&Bh[jA];
    const float2 bh_z = *(const float2*)&Bh[512 + jA];
    const float2 bh_n = *(const float2*)&Bh[1024 + jA];
    const int wsel = (j0 >> 1) + tg;

    const unsigned sb = (unsigned)__cvta_generic_to_shared(su);
    const unsigned aAddr = sb + ((SM_W) + (mt * 16 + (lane & 15)) * WS_STRIDE
                                 + (lane >> 4) * 4) * 4;
    const unsigned b4Hi = sb + (((lane & 15) * WS_STRIDE) + (lane >> 4) * 4) * 4;
    const unsigned b2Hi = sb + (((16 + (lane & 7)) * WS_STRIDE)
                                + ((lane >> 3) & 1) * 4) * 4;

    if (tid < 256) {
        int b = tid >> 2, w = (j0 >> 1) + (tid & 3);
        g_h[0][d][b * 256 + w] = 0u;
    }
    bar(0);

    const size_t HOFF = (size_t)BB * TT * 1024;

    for (int s = 0; s < TT; ++s) {
        const int p = s & 1;
        const int t = d ? (TT - 1 - s) : s;

        float2 air0, aiz0, ain0, air1, aiz1, ain1;
        if (kh == 0) {
            const float* z0p = &g_zi[d][t][b0i][0];
            const float* z1p = &g_zi[d][t][b1i][0];
            air0 = *(const float2*)&z0p[jA];
            aiz0 = *(const float2*)&z0p[512 + jA];
            ain0 = *(const float2*)&z0p[1024 + jA];
            air1 = *(const float2*)&z1p[jA];
            aiz1 = *(const float2*)&z1p[512 + jA];
            ain1 = *(const float2*)&z1p[1024 + jA];
        }

        // --- stage h in 4 chunks (single matrix now) ---
        {
            const unsigned* __restrict__ sh = g_h[p][d];
#pragma unroll
            for (int q = 0; q < 4; ++q) {
#pragma unroll
                for (int it = 0; it < 4; ++it) {
                    int j  = it * 256 + tid;               // 0..1023
                    int b  = j >> 4;
                    int cl = j & 15;
                    int c  = (cl < 8) ? (q * 8 + cl) : (32 + q * 8 + (cl - 8));
                    int idx = b * 64 + c;
                    unsigned dsth = sb + ((SM_W) + b * WS_STRIDE + c * 4) * 4;
                    cp_async16(dsth, sh + idx * 4);
                }
                asm volatile("cp.async.commit_group;\n");
            }
        }

        float ar[4], az[4], an[4];
#pragma unroll
        for (int i = 0; i < 4; i++) { ar[i] = 0.f; az[i] = 0.f; an[i] = 0.f; }

        const unsigned kbase = (unsigned)(kh * 128) * 4;
#pragma unroll
        for (int q = 0; q < 4; ++q) {
            if (q == 0)      asm volatile("cp.async.wait_group 3;\n");
            else if (q == 1) asm volatile("cp.async.wait_group 2;\n");
            else if (q == 2) asm volatile("cp.async.wait_group 1;\n");
            else             asm volatile("cp.async.wait_group 0;\n");
            __syncthreads();

#pragma unroll
            for (int ki = 0; ki < 4; ++ki) {
                const int ks = q * 4 + ki;
                const unsigned koff = kbase + ks * 32;
                unsigned Af[4];
                ldsm4(aAddr + koff, Af);
                unsigned BrzH[4], BnH[2];
                ldsm4(b4Hi + koff, BrzH);
                ldsm2(b2Hi + koff, BnH);
                unsigned brh[2] = {BrzH[0], BrzH[2]}, bzh[2] = {BrzH[1], BrzH[3]};
                mma16816h(ar, Af, brh);
                mma16816h(az, Af, bzh);
                mma16816h(an, Af, BnH);
            }
        }

        if (kh == 1) {
            float* xp = &X[(mt * 32 + lane) * X_STRIDE];
#pragma unroll
            for (int i = 0; i < 4; i++) {
                xp[i] = ar[i]; xp[4 + i] = az[i]; xp[8 + i] = an[i];
            }
        }
        __syncthreads();

        if (kh == 0) {
            const float* xp = &X[(mt * 32 + lane) * X_STRIDE];
#pragma unroll
            for (int i = 0; i < 4; i++) {
                ar[i] += xp[i]; az[i] += xp[4 + i]; an[i] += xp[8 + i];
            }

            unsigned uh0 = Hs[b0i * WS_STRIDE + wsel];
            unsigned uh1 = Hs[b1i * WS_STRIDE + wsel];
            float hp00 = lo16h(uh0);
            float hp01 = hi16h(uh0);
            float hp10 = lo16h(uh1);
            float hp11 = hi16h(uh1);

            float r00 = 1.f / (1.f + __expf(-(air0.x + ar[0] + bh_r.x)));
            float z00 = 1.f / (1.f + __expf(-(aiz0.x + az[0] + bh_z.x)));
            float n00 = tanhf(ain0.x + r00 * (an[0] + bh_n.x));
            float h00 = (1.f - z00) * n00 + z00 * hp00;

            float r01 = 1.f / (1.f + __expf(-(air0.y + ar[1] + bh_r.y)));
            float z01 = 1.f / (1.f + __expf(-(aiz0.y + az[1] + bh_z.y)));
            float n01 = tanhf(ain0.y + r01 * (an[1] + bh_n.y));
            float h01 = (1.f - z01) * n01 + z01 * hp01;

            float r10 = 1.f / (1.f + __expf(-(air1.x + ar[2] + bh_r.x)));
            float z10 = 1.f / (1.f + __expf(-(aiz1.x + az[2] + bh_z.x)));
            float n10 = tanhf(ain1.x + r10 * (an[2] + bh_n.x));
            float h10 = (1.f - z10) * n10 + z10 * hp10;

            float r11 = 1.f / (1.f + __expf(-(air1.y + ar[3] + bh_r.y)));
            float z11 = 1.f / (1.f + __expf(-(aiz1.y + az[3] + bh_z.y)));
            float n11 = tanhf(ain1.y + r11 * (an[3] + bh_n.y));
            float h11 = (1.f - z11) * n11 + z11 * hp11;

            g_h[p ^ 1][d][b0i * 256 + wsel] = pack2h(h00, h01);
            g_h[p ^ 1][d][b1i * 256 + wsel] = pack2h(h10, h11);

            float2 o0; o0.x = h00; o0.y = h01;
            float2 o1; o1.x = h10; o1.y = h11;
            *(float2*)&out[(size_t)(b0i * TT + t) * 1024 + d * 512 + jA] = o0;
            *(float2*)&out[(size_t)(b1i * TT + t) * 1024 + d * 512 + jA] = o1;
            if (s == TT - 1) {
                *(float2*)&out[HOFF + (size_t)d * BB * HH + b0i * HH + jA] = o0;
                *(float2*)&out[HOFF + (size_t)d * BB * HH + b1i * HH + jA] = o1;
            }
        }
        if (s < TT - 1) bar(s + 1);
    }

    if (tid == 0) {
        for (int i = sub; i < 512; i += 64) g_cnt[d][i] = 0u;
    }
}

// =================================================================
extern "C" void kernel_launch(void* const* d_in, const int* in_sizes, int n_in,
                              void* d_out, int out_size)
{
    const float* x       = (const float*)d_in[0];
    const float* w_ih_fw = (const float*)d_in[1];
    const float* w_hh_fw = (const float*)d_in[2];
    const float* b_ih_fw = (const float*)d_in[3];
    const float* b_hh_fw = (const float*)d_in[4];
    const float* w_ih_bw = (const float*)d_in[5];
    const float* w_hh_bw = (const float*)d_in[6];
    const float* b_ih_bw = (const float*)d_in[7];
    const float* b_hh_bw = (const float*)d_in[8];
    float* out = (float*)d_out;

    cudaFuncSetAttribute(gemm_zi_kernel, cudaFuncAttributeMaxDynamicSharedMemorySize,
                         GEMM_SMEM_BYTES);
    cudaFuncSetAttribute(rnn_kernel, cudaFuncAttributeMaxDynamicSharedMemorySize,
                         RNN_SMEM_BYTES);

    const unsigned total_words = XWRD + 2 * WWRD;
    convert_kernel<<<(total_words + 255) / 256, 256>>>(x, w_ih_fw, w_ih_bw);

    dim3 ggrid(G3 / 64, MTOT / 128, 2);
    gemm_zi_kernel<<<ggrid, 256, GEMM_SMEM_BYTES>>>(b_ih_fw, b_ih_bw);

    rnn_kernel<<<128, 256, RNN_SMEM_BYTES>>>(w_hh_fw, w_hh_bw, b_hh_fw, b_hh_bw, out);
}

// round 16
// speedup vs baseline: 1.3930x; 1.3930x over previous
#include <cuda_runtime.h>
#include <cuda_bf16.h>
#include <cuda_fp16.h>

#define BB 64
#define TT 512
#define DD 512
#define HH 512
#define G3 1536

#define MTOT (BB * TT)
#define KW   (DD / 2)
#define XWRD (MTOT * KW)
#define WWRD (G3 * KW)

// ---------------- device scratch (no allocations allowed) ----------------
__device__ float    g_zi[2][TT][BB][G3];
__device__ unsigned g_xhi[XWRD];              // x fp16x2 hi
__device__ unsigned g_xlo[XWRD];              // x fp16x2 lo
__device__ unsigned g_whi[2][WWRD];           // W_ih fp16x2
__device__ unsigned g_h[2][2][BB * 256];      // h fp16x2 (single precision)
__device__ unsigned g_cnt[2][512];

// =================================================================
// helpers
// =================================================================
__device__ __forceinline__ unsigned pack2h(float a, float b) {
    __half2 t = __floats2half2_rn(a, b);
    return reinterpret_cast<unsigned&>(t);
}
__device__ __forceinline__ void split2h(float a, float b, unsigned& hi, unsigned& lo) {
    __half ha = __float2half_rn(a), hb = __float2half_rn(b);
    __half2 th = __halves2half2(ha, hb);
    hi = reinterpret_cast<unsigned&>(th);
    lo = pack2h(a - __half2float(ha), b - __half2float(hb));
}
__device__ __forceinline__ float lo16h(unsigned u) {
    __half2 t = reinterpret_cast<__half2&>(u);
    return __half2float(t.x);
}
__device__ __forceinline__ float hi16h(unsigned u) {
    __half2 t = reinterpret_cast<__half2&>(u);
    return __half2float(t.y);
}
__device__ __forceinline__ void mma16816h(float* c, const unsigned* a, const unsigned* b) {
    asm volatile(
        "mma.sync.aligned.m16n8k16.row.col.f32.f16.f16.f32 "
        "{%0,%1,%2,%3}, {%4,%5,%6,%7}, {%8,%9}, {%0,%1,%2,%3};"
        : "+f"(c[0]), "+f"(c[1]), "+f"(c[2]), "+f"(c[3])
        : "r"(a[0]), "r"(a[1]), "r"(a[2]), "r"(a[3]), "r"(b[0]), "r"(b[1]));
}
__device__ __forceinline__ void cp_async16(unsigned smem_addr, const void* gptr) {
    asm volatile("cp.async.cg.shared.global [%0], [%1], 16;\n"
                 :: "r"(smem_addr), "l"(gptr));
}
__device__ __forceinline__ void ldsm4(unsigned addr, unsigned* r) {
    asm volatile("ldmatrix.sync.aligned.m8n8.x4.shared.b16 {%0,%1,%2,%3}, [%4];"
        : "=r"(r[0]), "=r"(r[1]), "=r"(r[2]), "=r"(r[3]) : "r"(addr));
}
__device__ __forceinline__ void ldsm2(unsigned addr, unsigned* r) {
    asm volatile("ldmatrix.sync.aligned.m8n8.x2.shared.b16 {%0,%1}, [%2];"
        : "=r"(r[0]), "=r"(r[1]) : "r"(addr));
}

// =================================================================
// Kernel 0: split x into fp16 hi/lo; W_ih into fp16
// (UNCHANGED — serves as the clock canary across rounds)
// =================================================================
__global__ void convert_kernel(const float* __restrict__ x,
                               const float* __restrict__ w_fw,
                               const float* __restrict__ w_bw)
{
    const unsigned idx = blockIdx.x * 256 + threadIdx.x;
    if (idx < XWRD) {
        float2 v = reinterpret_cast<const float2*>(x)[idx];
        split2h(v.x, v.y, g_xhi[idx], g_xlo[idx]);
    } else {
        unsigned w = idx - XWRD;
        if (w < 2u * WWRD) {
            int d = w >= WWRD;
            unsigned o = d ? w - WWRD : w;
            const float* src = d ? w_bw : w_fw;
            float2 v = reinterpret_cast<const float2*>(src)[o];
            g_whi[d][o] = pack2h(v.x, v.y);
        }
    }
}

// =================================================================
// Kernel 1: zi = x @ W_ih^T + b_ih  (unchanged from R13/R14)
// =================================================================
#define GS_ROWW 20
#define A_MAT (128 * GS_ROWW)
#define B_MAT (64 * GS_ROWW)
#define GEMM_SMEM_WORDS (6 * A_MAT + 3 * B_MAT)
#define GEMM_SMEM_BYTES (GEMM_SMEM_WORDS * 4)

__global__ void __launch_bounds__(256, 2) gemm_zi_kernel(
    const float* __restrict__ b_fw, const float* __restrict__ b_bw)
{
    extern __shared__ unsigned gsm[];
    const int d = blockIdx.z;
    const float* __restrict__ Bi = d ? b_bw : b_fw;
    const unsigned* __restrict__ wh = g_whi[d];
    float* __restrict__ zi = &g_zi[d][0][0][0];

    const int m0 = blockIdx.y * 128;
    const int n0 = blockIdx.x * 64;
    const int tid  = threadIdx.x;
    const int warp = tid >> 5;
    const int lane = tid & 31;
    const int g    = lane >> 2;
    const int tg   = lane & 3;
    const int wm   = warp >> 2;
    const int wn   = warp & 3;

    const unsigned smem_base = (unsigned)__cvta_generic_to_shared(gsm);

    auto load_stage = [&](int kt, int s) {
#pragma unroll
        for (int i = 0; i < 5; i++) {
            int id = i * 256 + tid;
            const unsigned* src;
            unsigned dstw;
            if (id < 512) {
                int r = id >> 2, c = id & 3;
                src = g_xhi + (size_t)(m0 + r) * KW + kt * 16 + c * 4;
                dstw = s * A_MAT + r * GS_ROWW + c * 4;
            } else if (id < 1024) {
                int rem = id - 512;
                int r = rem >> 2, c = rem & 3;
                src = g_xlo + (size_t)(m0 + r) * KW + kt * 16 + c * 4;
                dstw = (3 + s) * A_MAT + r * GS_ROWW + c * 4;
            } else {
                int rem = id - 1024;
                int r = rem >> 2, c = rem & 3;
                src = wh + (size_t)(n0 + r) * KW + kt * 16 + c * 4;
                dstw = 6 * A_MAT + s * B_MAT + r * GS_ROWW + c * 4;
            }
            cp_async16(smem_base + dstw * 4, src);
        }
        asm volatile("cp.async.commit_group;\n");
    };

    float acc[4][2][4];
#pragma unroll
    for (int mi = 0; mi < 4; mi++)
#pragma unroll
        for (int ni = 0; ni < 2; ni++)
#pragma unroll
            for (int i = 0; i < 4; i++) acc[mi][ni][i] = 0.f;

    load_stage(0, 0);
    load_stage(1, 1);

    const int lr = lane & 15;
    const int lh = (lane >> 4) * 4;

    for (int kt = 0; kt < 16; ++kt) {
        if (kt < 15) asm volatile("cp.async.wait_group 1;\n");
        else         asm volatile("cp.async.wait_group 0;\n");
        __syncthreads();

        if (kt + 2 < 16) load_stage(kt + 2, (kt + 2) % 3);

        const int st = kt % 3;
        const unsigned baseXH = smem_base + (st * A_MAT) * 4;
        const unsigned baseXL = smem_base + ((3 + st) * A_MAT) * 4;
        const unsigned baseWH = smem_base + (6 * A_MAT + st * B_MAT) * 4;

#pragma unroll
        for (int kk = 0; kk < 2; ++kk) {
            const int kw = kk * 8 + lh;
            unsigned bhi[4];
            {
                unsigned off = ((wn * 16 + lr) * GS_ROWW + kw) * 4;
                ldsm4(baseWH + off, bhi);
            }
            unsigned be[2] = {bhi[0], bhi[2]};
            unsigned bo[2] = {bhi[1], bhi[3]};
#pragma unroll
            for (int mi = 0; mi < 4; mi++) {
                unsigned ahi[4], alo[4];
                unsigned off = ((wm * 64 + mi * 16 + lr) * GS_ROWW + kw) * 4;
                ldsm4(baseXH + off, ahi);
                ldsm4(baseXL + off, alo);
                mma16816h(acc[mi][0], ahi, be);
                mma16816h(acc[mi][0], alo, be);
                mma16816h(acc[mi][1], ahi, bo);
                mma16816h(acc[mi][1], alo, bo);
            }
        }
    }

    float bias[2][2];
#pragma unroll
    for (int ni = 0; ni < 2; ni++) {
        const int n = n0 + wn * 16 + ni * 8 + tg * 2;
        bias[ni][0] = Bi[n]; bias[ni][1] = Bi[n + 1];
    }
#pragma unroll
    for (int mi = 0; mi < 4; mi++) {
        const int row0 = m0 + wm * 64 + mi * 16 + g;
        const int row1 = row0 + 8;
        const int t0 = row0 & (TT - 1), b0r = row0 >> 9;
        const int t1 = row1 & (TT - 1), b1r = row1 >> 9;
        float* d0 = zi + (size_t)(t0 * BB + b0r) * G3;
        float* d1 = zi + (size_t)(t1 * BB + b1r) * G3;
#pragma unroll
        for (int ni = 0; ni < 2; ni++) {
            const int n = n0 + wn * 16 + ni * 8 + tg * 2;
            float2 v0, v1;
            v0.x = acc[mi][ni][0] + bias[ni][0];
            v0.y = acc[mi][ni][1] + bias[ni][1];
            v1.x = acc[mi][ni][2] + bias[ni][0];
            v1.y = acc[mi][ni][3] + bias[ni][1];
            *(float2*)(d0 + n) = v0;
            *(float2*)(d1 + n) = v1;
        }
    }
}

// =================================================================
// Kernel 2: persistent recurrence, SINGLE fp16 h carry (as R15):
// 3 MMAs + 3 LDSM per k16; staging 64 KB/block/step.
// =================================================================
#define WS_STRIDE 260
#define SM_W (24 * WS_STRIDE)
#define SM_H (64 * WS_STRIDE)
#define X_STRIDE 13
#define SM_X (4 * 32 * X_STRIDE)
#define RNN_SMEM_BYTES ((SM_W + SM_H + SM_X) * 4)

__global__ void __launch_bounds__(256, 1) rnn_kernel(
    const float* __restrict__ whh_fw, const float* __restrict__ whh_bw,
    const float* __restrict__ bhh_fw, const float* __restrict__ bhh_bw,
    float* __restrict__ out)
{
    extern __shared__ unsigned su[];
    unsigned* WHi = su;
    unsigned* Hs  = su + SM_W;
    float*    X   = (float*)(su + SM_W + SM_H);

    const int bid = blockIdx.x;
    const int d   = bid >> 6;
    const int sub = bid & 63;
    const int j0  = sub * 8;
    const float* __restrict__ W  = d ? whh_bw : whh_fw;
    const float* __restrict__ Bh = d ? bhh_bw : bhh_fw;

    const int tid  = threadIdx.x;
    const int warp = tid >> 5;
    const int lane = tid & 31;
    const int mt   = warp & 3;
    const int kh   = warp >> 2;
    const int g    = lane >> 2;
    const int tg   = lane & 3;

    auto bar = [&](int idx) {
        __syncthreads();
        if (tid == 0) {
            __threadfence();
            atomicAdd(&g_cnt[d][idx], 1u);
            unsigned v;
            do {
                v = *((volatile unsigned*)&g_cnt[d][idx]);
            } while (v != 0u && v < 64u);
            __threadfence();
        }
        __syncthreads();
    };

    for (int idx = tid; idx < 24 * 256; idx += 256) {
        int r = idx >> 8, kw = idx & 255;
        int grow = ((r >> 3) << 9) + j0 + (r & 7);
        const float* wr = W + (size_t)grow * HH + kw * 2;
        WHi[r * WS_STRIDE + kw] = pack2h(wr[0], wr[1]);
    }

    const int b0i = mt * 16 + g;
    const int b1i = b0i + 8;
    const int jA  = j0 + tg * 2;
    const float2 bh_r = *(const float2*)&Bh[jA];
    const float2 bh_z = *(const float2*)&Bh[512 + jA];
    const float2 bh_n = *(const float2*)&Bh[1024 + jA];
    const int wsel = (j0 >> 1) + tg;

    const unsigned sb = (unsigned)__cvta_generic_to_shared(su);
    const unsigned aAddr = sb + ((SM_W) + (mt * 16 + (lane & 15)) * WS_STRIDE
                                 + (lane >> 4) * 4) * 4;
    const unsigned b4Hi = sb + (((lane & 15) * WS_STRIDE) + (lane >> 4) * 4) * 4;
    const unsigned b2Hi = sb + (((16 + (lane & 7)) * WS_STRIDE)
                                + ((lane >> 3) & 1) * 4) * 4;

    if (tid < 256) {
        int b = tid >> 2, w = (j0 >> 1) + (tid & 3);
        g_h[0][d][b * 256 + w] = 0u;
    }
    bar(0);

    const size_t HOFF = (size_t)BB * TT * 1024;

    for (int s = 0; s < TT; ++s) {
        const int p = s & 1;
        const int t = d ? (TT - 1 - s) : s;

        float2 air0, aiz0, ain0, air1, aiz1, ain1;
        if (kh == 0) {
            const float* z0p = &g_zi[d][t][b0i][0];
            const float* z1p = &g_zi[d][t][b1i][0];
            air0 = *(const float2*)&z0p[jA];
            aiz0 = *(const float2*)&z0p[512 + jA];
            ain0 = *(const float2*)&z0p[1024 + jA];
            air1 = *(const float2*)&z1p[jA];
            aiz1 = *(const float2*)&z1p[512 + jA];
            ain1 = *(const float2*)&z1p[1024 + jA];
        }

        {
            const unsigned* __restrict__ sh = g_h[p][d];
#pragma unroll
            for (int q = 0; q < 4; ++q) {
#pragma unroll
                for (int it = 0; it < 4; ++it) {
                    int j  = it * 256 + tid;
                    int b  = j >> 4;
                    int cl = j & 15;
                    int c  = (cl < 8) ? (q * 8 + cl) : (32 + q * 8 + (cl - 8));
                    int idx = b * 64 + c;
                    unsigned dsth = sb + ((SM_W) + b * WS_STRIDE + c * 4) * 4;
                    cp_async16(dsth, sh + idx * 4);
                }
                asm volatile("cp.async.commit_group;\n");
            }
        }

        float ar[4], az[4], an[4];
#pragma unroll
        for (int i = 0; i < 4; i++) { ar[i] = 0.f; az[i] = 0.f; an[i] = 0.f; }

        const unsigned kbase = (unsigned)(kh * 128) * 4;
#pragma unroll
        for (int q = 0; q < 4; ++q) {
            if (q == 0)      asm volatile("cp.async.wait_group 3;\n");
            else if (q == 1) asm volatile("cp.async.wait_group 2;\n");
            else if (q == 2) asm volatile("cp.async.wait_group 1;\n");
            else             asm volatile("cp.async.wait_group 0;\n");
            __syncthreads();

#pragma unroll
            for (int ki = 0; ki < 4; ++ki) {
                const int ks = q * 4 + ki;
                const unsigned koff = kbase + ks * 32;
                unsigned Af[4];
                ldsm4(aAddr + koff, Af);
                unsigned BrzH[4], BnH[2];
                ldsm4(b4Hi + koff, BrzH);
                ldsm2(b2Hi + koff, BnH);
                unsigned brh[2] = {BrzH[0], BrzH[2]}, bzh[2] = {BrzH[1], BrzH[3]};
                mma16816h(ar, Af, brh);
                mma16816h(az, Af, bzh);
                mma16816h(an, Af, BnH);
            }
        }

        if (kh == 1) {
            float* xp = &X[(mt * 32 + lane) * X_STRIDE];
#pragma unroll
            for (int i = 0; i < 4; i++) {
                xp[i] = ar[i]; xp[4 + i] = az[i]; xp[8 + i] = an[i];
            }
        }
        __syncthreads();

        if (kh == 0) {
            const float* xp = &X[(mt * 32 + lane) * X_STRIDE];
#pragma unroll
            for (int i = 0; i < 4; i++) {
                ar[i] += xp[i]; az[i] += xp[4 + i]; an[i] += xp[8 + i];
            }

            unsigned uh0 = Hs[b0i * WS_STRIDE + wsel];
            unsigned uh1 = Hs[b1i * WS_STRIDE + wsel];
            float hp00 = lo16h(uh0);
            float hp01 = hi16h(uh0);
            float hp10 = lo16h(uh1);
            float hp11 = hi16h(uh1);

            float r00 = 1.f / (1.f + __expf(-(air0.x + ar[0] + bh_r.x)));
            float z00 = 1.f / (1.f + __expf(-(aiz0.x + az[0] + bh_z.x)));
            float n00 = tanhf(ain0.x + r00 * (an[0] + bh_n.x));
            float h00 = (1.f - z00) * n00 + z00 * hp00;

            float r01 = 1.f / (1.f + __expf(-(air0.y + ar[1] + bh_r.y)));
            float z01 = 1.f / (1.f + __expf(-(aiz0.y + az[1] + bh_z.y)));
            float n01 = tanhf(ain0.y + r01 * (an[1] + bh_n.y));
            float h01 = (1.f - z01) * n01 + z01 * hp01;

            float r10 = 1.f / (1.f + __expf(-(air1.x + ar[2] + bh_r.x)));
            float z10 = 1.f / (1.f + __expf(-(aiz1.x + az[2] + bh_z.x)));
            float n10 = tanhf(ain1.x + r10 * (an[2] + bh_n.x));
            float h10 = (1.f - z10) * n10 + z10 * hp10;

            float r11 = 1.f / (1.f + __expf(-(air1.y + ar[3] + bh_r.y)));
            float z11 = 1.f / (1.f + __expf(-(aiz1.y + az[3] + bh_z.y)));
            float n11 = tanhf(ain1.y + r11 * (an[3] + bh_n.y));
            float h11 = (1.f - z11) * n11 + z11 * hp11;

            g_h[p ^ 1][d][b0i * 256 + wsel] = pack2h(h00, h01);
            g_h[p ^ 1][d][b1i * 256 + wsel] = pack2h(h10, h11);

            float2 o0; o0.x = h00; o0.y = h01;
            float2 o1; o1.x = h10; o1.y = h11;
            *(float2*)&out[(size_t)(b0i * TT + t) * 1024 + d * 512 + jA] = o0;
            *(float2*)&out[(size_t)(b1i * TT + t) * 1024 + d * 512 + jA] = o1;
            if (s == TT - 1) {
                *(float2*)&out[HOFF + (size_t)d * BB * HH + b0i * HH + jA] = o0;
                *(float2*)&out[HOFF + (size_t)d * BB * HH + b1i * HH + jA] = o1;
            }
        }
        if (s < TT - 1) bar(s + 1);
    }

    if (tid == 0) {
        for (int i = sub; i < 512; i += 64) g_cnt[d][i] = 0u;
    }
}

// =================================================================
extern "C" void kernel_launch(void* const* d_in, const int* in_sizes, int n_in,
                              void* d_out, int out_size)
{
    const float* x       = (const float*)d_in[0];
    const float* w_ih_fw = (const float*)d_in[1];
    const float* w_hh_fw = (const float*)d_in[2];
    const float* b_ih_fw = (const float*)d_in[3];
    const float* b_hh_fw = (const float*)d_in[4];
    const float* w_ih_bw = (const float*)d_in[5];
    const float* w_hh_bw = (const float*)d_in[6];
    const float* b_ih_bw = (const float*)d_in[7];
    const float* b_hh_bw = (const float*)d_in[8];
    float* out = (float*)d_out;

    cudaFuncSetAttribute(gemm_zi_kernel, cudaFuncAttributeMaxDynamicSharedMemorySize,
                         GEMM_SMEM_BYTES);
    cudaFuncSetAttribute(rnn_kernel, cudaFuncAttributeMaxDynamicSharedMemorySize,
                         RNN_SMEM_BYTES);

    const unsigned total_words = XWRD + 2 * WWRD;
    convert_kernel<<<(total_words + 255) / 256, 256>>>(x, w_ih_fw, w_ih_bw);

    dim3 ggrid(G3 / 64, MTOT / 128, 2);
    gemm_zi_kernel<<<ggrid, 256, GEMM_SMEM_BYTES>>>(b_ih_fw, b_ih_bw);

    rnn_kernel<<<128, 256, RNN_SMEM_BYTES>>>(w_hh_fw, w_hh_bw, b_hh_fw, b_hh_bw, out);
}